// round 4
// baseline (speedup 1.0000x reference)
#include <cuda_runtime.h>
#include <math.h>

#define B_DIM 4096
#define I_DIM 1024
#define O_DIM 1024
#define NDEG 4   // degrees 1..4 go through the GEMM; degree 0 becomes a bias

// ---- scratch (static device globals: no allocation anywhere) ----
__device__ float g_h[B_DIM * I_DIM];          // tanh(layernorm(x))
__device__ float g_Ct[NDEG][I_DIM * O_DIM];   // per-degree coeff planes, [i*O + o]
__device__ float g_bias[O_DIM];               // sum_i C[i,o,0]

// ---------------- packed f32x2 helpers ----------------
__device__ __forceinline__ unsigned long long pk2(float x) {
    unsigned long long r;
    asm("mov.b64 %0, {%1, %1};" : "=l"(r) : "r"(__float_as_uint(x)));
    return r;
}
__device__ __forceinline__ unsigned long long ffma2(unsigned long long a,
                                                    unsigned long long b,
                                                    unsigned long long c) {
    unsigned long long d;
    asm("fma.rn.f32x2 %0, %1, %2, %3;" : "=l"(d) : "l"(a), "l"(b), "l"(c));
    return d;
}

// ---------------- kernel 1: layernorm + tanh ----------------
__global__ void ln_tanh_kernel(const float* __restrict__ x,
                               const float* __restrict__ w,
                               const float* __restrict__ b) {
    int row = blockIdx.x;
    int tid = threadIdx.x;          // 256 threads, 1 float4 each
    float4 v = ((const float4*)(x + (size_t)row * I_DIM))[tid];
    float s  = v.x + v.y + v.z + v.w;
    float ss = v.x * v.x + v.y * v.y + v.z * v.z + v.w * v.w;
    #pragma unroll
    for (int o = 16; o > 0; o >>= 1) {
        s  += __shfl_down_sync(0xffffffffu, s, o);
        ss += __shfl_down_sync(0xffffffffu, ss, o);
    }
    __shared__ float rs[8], rss[8];
    __shared__ float s_mu, s_rstd;
    int wid = tid >> 5, lid = tid & 31;
    if (lid == 0) { rs[wid] = s; rss[wid] = ss; }
    __syncthreads();
    if (tid == 0) {
        float ts = 0.f, tss = 0.f;
        #pragma unroll
        for (int i = 0; i < 8; i++) { ts += rs[i]; tss += rss[i]; }
        float mu  = ts * (1.0f / I_DIM);
        float var = tss * (1.0f / I_DIM) - mu * mu;
        s_mu = mu;
        s_rstd = rsqrtf(var + 1e-5f);
    }
    __syncthreads();
    float mu = s_mu, rstd = s_rstd;
    float4 wv = ((const float4*)w)[tid];
    float4 bv = ((const float4*)b)[tid];
    float4 h;
    h.x = tanhf((v.x - mu) * rstd * wv.x + bv.x);
    h.y = tanhf((v.y - mu) * rstd * wv.y + bv.y);
    h.z = tanhf((v.z - mu) * rstd * wv.z + bv.z);
    h.w = tanhf((v.w - mu) * rstd * wv.w + bv.w);
    ((float4*)(g_h + (size_t)row * I_DIM))[tid] = h;
}

// ---------------- kernel 2: split C[i,o,d] into degree planes ----------------
__global__ void prep_coeff_kernel(const float* __restrict__ C) {
    int i = blockIdx.x;
    int o0 = threadIdx.x * 4;                       // 4 outputs per thread
    const float* c = C + (size_t)i * (O_DIM * 5) + (size_t)o0 * 5;
    float d1[4], d2[4], d3[4], d4[4];
    #pragma unroll
    for (int j = 0; j < 4; j++) {
        const float* cj = c + j * 5;
        d1[j] = cj[1]; d2[j] = cj[2]; d3[j] = cj[3]; d4[j] = cj[4];
    }
    size_t idx = (size_t)i * O_DIM + o0;
    *(float4*)&g_Ct[0][idx] = make_float4(d1[0], d1[1], d1[2], d1[3]);
    *(float4*)&g_Ct[1][idx] = make_float4(d2[0], d2[1], d2[2], d2[3]);
    *(float4*)&g_Ct[2][idx] = make_float4(d3[0], d3[1], d3[2], d3[3]);
    *(float4*)&g_Ct[3][idx] = make_float4(d4[0], d4[1], d4[2], d4[3]);
}

// ---------------- kernel 3: degree-0 bias = column sum (deterministic) -------
__global__ void bias_kernel(const float* __restrict__ C) {
    int o = blockIdx.x;
    int tid = threadIdx.x;
    float s = 0.f;
    for (int i = tid; i < I_DIM; i += 256)
        s += C[(size_t)i * (O_DIM * 5) + o * 5];       // d = 0
    #pragma unroll
    for (int off = 16; off > 0; off >>= 1)
        s += __shfl_down_sync(0xffffffffu, s, off);
    __shared__ float rs[8];
    if ((tid & 31) == 0) rs[tid >> 5] = s;
    __syncthreads();
    if (tid == 0) {
        float t = 0.f;
        #pragma unroll
        for (int k = 0; k < 8; k++) t += rs[k];
        g_bias[o] = t;
    }
}

// ---------------- kernel 4: 4-plane GEMM + bias + silu ----------------
#define BM 128
#define BN 128
#define BK 8
#define PAD_LD 132   // 128 + 4 pad; 528B rows keep 16B alignment, kill STS conflicts

__global__ __launch_bounds__(256, 2)
void cheby_gemm_kernel(float* __restrict__ out) {
    __shared__ float As[NDEG][BK][PAD_LD];   // T_d of h, [d][k][m]
    __shared__ float Bs[NDEG][BK][PAD_LD];   // coeff planes, [d][k][n]

    int tid = threadIdx.x;
    int row0 = blockIdx.x * BM;
    int col0 = blockIdx.y * BN;
    int tx = tid & 15;          // n-tile: 8 cols
    int ty = tid >> 4;          // m-tile: 8 rows

    // A fill: each thread loads one float4 of h (row m_a, 4 k's)
    int m_a = tid >> 1;
    int ka4 = (tid & 1) * 4;
    // B fill: per degree, one float4 (row kb, 4 n's)
    int kb  = tid >> 5;
    int nb4 = (tid & 31) * 4;

    const float* hrow = g_h + (size_t)(row0 + m_a) * I_DIM + ka4;

    unsigned long long acc[8][4];
    #pragma unroll
    for (int m = 0; m < 8; m++)
        #pragma unroll
        for (int n = 0; n < 4; n++) acc[m][n] = 0ull;

    // prefetch tile 0 into registers
    float4 pa = *(const float4*)(hrow);
    float4 pb[NDEG];
    #pragma unroll
    for (int d = 0; d < NDEG; d++)
        pb[d] = *(const float4*)(g_Ct[d] + (size_t)kb * O_DIM + col0 + nb4);

    const int NT = I_DIM / BK;
    for (int t = 0; t < NT; t++) {
        // registers -> smem (compute Chebyshev T1..T4 on the way in)
        {
            float h0[4] = {pa.x, pa.y, pa.z, pa.w};
            #pragma unroll
            for (int j = 0; j < 4; j++) {
                float t1 = h0[j];
                float t2 = 2.f * t1 * t1 - 1.f;
                float t3 = 2.f * t1 * t2 - t1;
                float t4 = 2.f * t1 * t3 - t2;
                As[0][ka4 + j][m_a] = t1;
                As[1][ka4 + j][m_a] = t2;
                As[2][ka4 + j][m_a] = t3;
                As[3][ka4 + j][m_a] = t4;
            }
            #pragma unroll
            for (int d = 0; d < NDEG; d++)
                *(float4*)&Bs[d][kb][nb4] = pb[d];
        }
        __syncthreads();

        // prefetch next tile (overlaps gmem latency with compute below)
        if (t + 1 < NT) {
            pa = *(const float4*)(hrow + (size_t)(t + 1) * BK);
            #pragma unroll
            for (int d = 0; d < NDEG; d++)
                pb[d] = *(const float4*)(g_Ct[d] +
                          ((size_t)(t + 1) * BK + kb) * O_DIM + col0 + nb4);
        }

        #pragma unroll
        for (int k = 0; k < BK; k++) {
            #pragma unroll
            for (int d = 0; d < NDEG; d++) {
                float4 a0 = *(const float4*)&As[d][k][ty * 8];
                float4 a1 = *(const float4*)&As[d][k][ty * 8 + 4];
                ulonglong2 b0 = *(const ulonglong2*)&Bs[d][k][tx * 8];
                ulonglong2 b1 = *(const ulonglong2*)&Bs[d][k][tx * 8 + 4];
                unsigned long long bb[4] = {b0.x, b0.y, b1.x, b1.y};
                float av[8] = {a0.x, a0.y, a0.z, a0.w, a1.x, a1.y, a1.z, a1.w};
                #pragma unroll
                for (int m = 0; m < 8; m++) {
                    unsigned long long am = pk2(av[m]);
                    #pragma unroll
                    for (int n = 0; n < 4; n++)
                        acc[m][n] = ffma2(am, bb[n], acc[m][n]);
                }
            }
        }
        __syncthreads();
    }

    // epilogue: + bias (T0 term), then silu, coalesced float4 stores
    float bias_v[8];
    #pragma unroll
    for (int n = 0; n < 8; n++) bias_v[n] = g_bias[col0 + tx * 8 + n];

    #pragma unroll
    for (int m = 0; m < 8; m++) {
        float r[8];
        #pragma unroll
        for (int np = 0; np < 4; np++) {
            unsigned long long p = acc[m][np];
            r[2 * np]     = __uint_as_float((unsigned)(p & 0xffffffffull));
            r[2 * np + 1] = __uint_as_float((unsigned)(p >> 32));
        }
        float o[8];
        #pragma unroll
        for (int n = 0; n < 8; n++) {
            float y = r[n] + bias_v[n];
            o[n] = y * (1.f / (1.f + __expf(-y)));   // silu (fast exp)
        }
        float* orow = out + (size_t)(row0 + ty * 8 + m) * O_DIM + col0 + tx * 8;
        ((float4*)orow)[0] = make_float4(o[0], o[1], o[2], o[3]);
        ((float4*)orow)[1] = make_float4(o[4], o[5], o[6], o[7]);
    }
}

// ---------------- launch ----------------
extern "C" void kernel_launch(void* const* d_in, const int* in_sizes, int n_in,
                              void* d_out, int out_size) {
    const float* x  = (const float*)d_in[0];   // [4096,1024]
    const float* C  = (const float*)d_in[1];   // [1024,1024,5]
    const float* w  = (const float*)d_in[2];   // [1024]
    const float* b  = (const float*)d_in[3];   // [1024]
    float* out = (float*)d_out;                // [4096,1024]

    ln_tanh_kernel<<<B_DIM, 256>>>(x, w, b);
    prep_coeff_kernel<<<I_DIM, 256>>>(C);
    bias_kernel<<<O_DIM, 256>>>(C);
    cheby_gemm_kernel<<<dim3(B_DIM / BM, O_DIM / BN), 256>>>(out);
}

// round 7
// speedup vs baseline: 6.2108x; 6.2108x over previous
#include <cuda_runtime.h>
#include <cuda_fp16.h>
#include <math.h>
#include <stdint.h>

#define B_DIM 4096
#define I_DIM 1024
#define O_DIM 1024
#define KTOT  4096            // 4 degree planes * 1024

// ---- scratch (static device globals: no allocation anywhere) ----
__device__ __half g_A[(size_t)B_DIM * KTOT];   // fp16 Chebyshev features [b][k']
__device__ __half g_W[(size_t)O_DIM * KTOT];   // fp16 coeffs transposed  [o][k']
__device__ float  g_bias[O_DIM];               // sum_i C[i,o,0]

// ================= helpers =================
__device__ __forceinline__ uint32_t smem_u32(const void* p) {
    uint32_t a;
    asm("{ .reg .u64 t; cvta.to.shared.u64 t, %1; cvt.u32.u64 %0, t; }"
        : "=r"(a) : "l"(p));
    return a;
}
__device__ __forceinline__ void ldsm4(uint32_t* r, uint32_t addr) {
    asm volatile("ldmatrix.sync.aligned.m8n8.x4.shared.b16 {%0,%1,%2,%3}, [%4];"
                 : "=r"(r[0]), "=r"(r[1]), "=r"(r[2]), "=r"(r[3]) : "r"(addr));
}
__device__ __forceinline__ void mma16816(float* c, const uint32_t* a,
                                         uint32_t b0, uint32_t b1) {
    asm volatile(
        "mma.sync.aligned.m16n8k16.row.col.f32.f16.f16.f32 "
        "{%0,%1,%2,%3}, {%4,%5,%6,%7}, {%8,%9}, {%0,%1,%2,%3};"
        : "+f"(c[0]), "+f"(c[1]), "+f"(c[2]), "+f"(c[3])
        : "r"(a[0]), "r"(a[1]), "r"(a[2]), "r"(a[3]), "r"(b0), "r"(b1));
}
__device__ __forceinline__ void cpasync16(uint32_t dst, const void* src) {
    asm volatile("cp.async.cg.shared.global [%0], [%1], 16;" :: "r"(dst), "l"(src));
}

// ================= kernel 1: LN + tanh + Chebyshev features (fp16) =========
__global__ void ln_feat_kernel(const float* __restrict__ x,
                               const float* __restrict__ w,
                               const float* __restrict__ b) {
    int row = blockIdx.x;
    int tid = threadIdx.x;                 // 256 threads, 4 elements each
    float4 v = ((const float4*)(x + (size_t)row * I_DIM))[tid];
    float s  = v.x + v.y + v.z + v.w;
    float ss = v.x * v.x + v.y * v.y + v.z * v.z + v.w * v.w;
    #pragma unroll
    for (int o = 16; o > 0; o >>= 1) {
        s  += __shfl_down_sync(0xffffffffu, s, o);
        ss += __shfl_down_sync(0xffffffffu, ss, o);
    }
    __shared__ float rs[8], rss[8];
    __shared__ float s_mu, s_rstd;
    int wid = tid >> 5, lid = tid & 31;
    if (lid == 0) { rs[wid] = s; rss[wid] = ss; }
    __syncthreads();
    if (tid == 0) {
        float ts = 0.f, tss = 0.f;
        #pragma unroll
        for (int i = 0; i < 8; i++) { ts += rs[i]; tss += rss[i]; }
        float mu  = ts * (1.0f / I_DIM);
        float var = tss * (1.0f / I_DIM) - mu * mu;
        s_mu = mu; s_rstd = rsqrtf(var + 1e-5f);
    }
    __syncthreads();
    float mu = s_mu, rstd = s_rstd;
    float4 wv = ((const float4*)w)[tid];
    float4 bv = ((const float4*)b)[tid];
    float h[4];
    h[0] = tanhf((v.x - mu) * rstd * wv.x + bv.x);
    h[1] = tanhf((v.y - mu) * rstd * wv.y + bv.y);
    h[2] = tanhf((v.z - mu) * rstd * wv.z + bv.z);
    h[3] = tanhf((v.w - mu) * rstd * wv.w + bv.w);

    float t[4][4];                         // [degree-1][element]
    #pragma unroll
    for (int j = 0; j < 4; j++) {
        float h2 = h[j] + h[j];
        t[0][j] = h[j];
        t[1][j] = h2 * h[j] - 1.f;
        t[2][j] = h2 * t[1][j] - h[j];
        t[3][j] = h2 * t[2][j] - t[1][j];
    }
    int i0 = tid * 4;
    #pragma unroll
    for (int d = 0; d < 4; d++) {
        __half2 p0 = __floats2half2_rn(t[d][0], t[d][1]);
        __half2 p1 = __floats2half2_rn(t[d][2], t[d][3]);
        size_t off = (size_t)row * KTOT + d * I_DIM + i0;
        uint2 pk;
        pk.x = *(uint32_t*)&p0;
        pk.y = *(uint32_t*)&p1;
        *(uint2*)&g_A[off] = pk;
    }
}

// ================= kernel 2: coeff transpose to fp16 =================
// C[i,o,d] -> g_W[o][d*1024+i], 32x32 (i,o) tiles via smem transpose.
__global__ void prep_w_kernel(const float* __restrict__ C) {
    __shared__ __align__(16) __half sh[4][32][36];
    int i0 = blockIdx.x * 32, o0 = blockIdx.y * 32;
    int tid = threadIdx.x;
    #pragma unroll
    for (int j = 0; j < 4; j++) {
        int p = tid + 256 * j;
        int r = p >> 5, c = p & 31;        // r = local i, c = local o
        const float* base = C + ((size_t)(i0 + r) * O_DIM + (o0 + c)) * 5;
        #pragma unroll
        for (int d = 0; d < 4; d++)
            sh[d][c][r] = __float2half_rn(base[d + 1]);
    }
    __syncthreads();
    int oc = tid >> 3, icb = (tid & 7) * 4;
    #pragma unroll
    for (int d = 0; d < 4; d++) {
        uint2 vh = *(const uint2*)&sh[d][oc][icb];
        size_t off = (size_t)(o0 + oc) * KTOT + d * I_DIM + i0 + icb;
        *(uint2*)&g_W[off] = vh;
    }
}

// ================= kernel 3: degree-0 bias (deterministic) =================
__global__ void bias_kernel(const float* __restrict__ C) {
    int o = blockIdx.x;
    int tid = threadIdx.x;
    float s = 0.f;
    for (int i = tid; i < I_DIM; i += 256)
        s += C[(size_t)i * (O_DIM * 5) + o * 5];
    #pragma unroll
    for (int off = 16; off > 0; off >>= 1)
        s += __shfl_down_sync(0xffffffffu, s, off);
    __shared__ float rs[8];
    if ((tid & 31) == 0) rs[tid >> 5] = s;
    __syncthreads();
    if (tid == 0) {
        float t = 0.f;
        #pragma unroll
        for (int k = 0; k < 8; k++) t += rs[k];
        g_bias[o] = t;
    }
}

// ================= kernel 4: HMMA GEMM + bias + silu =================
// Block 128x128, 8 warps in 2(m) x 4(n); warp tile 64x32; k-chunk 64,
// cp.async double buffer, 128B-row XOR swizzle (conflict-free ldmatrix).
#define BM 128
#define BN 128
#define BKC 64
#define NT (KTOT / BKC)         // 64
#define TILE_BYTES (128 * 128)  // 128 rows * 64 halves (128B)
#define SMEM_TOTAL (1024 + 4 * TILE_BYTES)   // bias + 2*A + 2*B = 66560

__global__ __launch_bounds__(256, 2) void cheby_mma_gemm(float* __restrict__ out) {
    extern __shared__ char smem[];
    float* bias_s = (float*)smem;
    char* Abuf = smem + 1024;
    char* Bbuf = smem + 1024 + 2 * TILE_BYTES;

    int tid = threadIdx.x, lane = tid & 31, wid = tid >> 5;
    int warp_m = wid >> 2, warp_n = wid & 3;
    int row0 = blockIdx.x * BM, col0 = blockIdx.y * BN;
    if (tid < 128) bias_s[tid] = g_bias[col0 + tid];

    const __half* Ag = g_A + (size_t)row0 * KTOT;
    const __half* Wg = g_W + (size_t)col0 * KTOT;

    float acc[4][4][4];
    #pragma unroll
    for (int mt = 0; mt < 4; mt++)
        #pragma unroll
        for (int nt = 0; nt < 4; nt++)
            #pragma unroll
            for (int q = 0; q < 4; q++) acc[mt][nt][q] = 0.f;

    // per-thread load slots: 4 x 16B per tile
    int ldr[4], ldc[4], ldo[4];
    #pragma unroll
    for (int j = 0; j < 4; j++) {
        int ch = tid + 256 * j;            // 1024 chunks of 16B
        ldr[j] = ch >> 3;
        ldc[j] = ch & 7;
        ldo[j] = ldr[j] * 128 + ((ldc[j] ^ (ldr[j] & 7)) << 4);
    }

    // issue chunk 0
    {
        uint32_t ad = smem_u32(Abuf), bd = smem_u32(Bbuf);
        #pragma unroll
        for (int j = 0; j < 4; j++) {
            cpasync16(ad + ldo[j], Ag + (size_t)ldr[j] * KTOT + ldc[j] * 8);
            cpasync16(bd + ldo[j], Wg + (size_t)ldr[j] * KTOT + ldc[j] * 8);
        }
        asm volatile("cp.async.commit_group;");
    }

    int q = lane >> 3, lr = lane & 7;

    for (int t = 0; t < NT; t++) {
        if (t + 1 < NT) {
            int buf = (t + 1) & 1;
            int kb = (t + 1) * BKC;
            uint32_t ad = smem_u32(Abuf + buf * TILE_BYTES);
            uint32_t bd = smem_u32(Bbuf + buf * TILE_BYTES);
            #pragma unroll
            for (int j = 0; j < 4; j++) {
                cpasync16(ad + ldo[j], Ag + (size_t)ldr[j] * KTOT + kb + ldc[j] * 8);
                cpasync16(bd + ldo[j], Wg + (size_t)ldr[j] * KTOT + kb + ldc[j] * 8);
            }
            asm volatile("cp.async.commit_group;");
            asm volatile("cp.async.wait_group 1;");
        } else {
            asm volatile("cp.async.wait_group 0;");
        }
        __syncthreads();

        int buf = t & 1;
        uint32_t abase = smem_u32(Abuf + buf * TILE_BYTES);
        uint32_t bbase = smem_u32(Bbuf + buf * TILE_BYTES);

        #pragma unroll
        for (int s = 0; s < 4; s++) {
            // A frags: groups q0: r0-7/klo, q1: r8-15/klo, q2: r0-7/khi, q3: r8-15/khi
            uint32_t a[4][4];
            #pragma unroll
            for (int mt = 0; mt < 4; mt++) {
                int r = warp_m * 64 + mt * 16 + lr + (q & 1) * 8;
                int c16 = 2 * s + (q >> 1);
                ldsm4(a[mt], abase + r * 128 + ((c16 ^ (r & 7)) << 4));
            }
            // B frags: q0: n0-7/klo, q1: n0-7/khi, q2: n8-15/klo, q3: n8-15/khi
            uint32_t bfr[2][4];
            #pragma unroll
            for (int p = 0; p < 2; p++) {
                int r = warp_n * 32 + p * 16 + lr + (q >> 1) * 8;
                int c16 = 2 * s + (q & 1);
                ldsm4(bfr[p], bbase + r * 128 + ((c16 ^ (r & 7)) << 4));
            }
            #pragma unroll
            for (int mt = 0; mt < 4; mt++) {
                #pragma unroll
                for (int nt = 0; nt < 4; nt++) {
                    int p = nt >> 1, e = (nt & 1) * 2;
                    mma16816(acc[mt][nt], a[mt], bfr[p][e], bfr[p][e + 1]);
                }
            }
        }
        __syncthreads();
    }

    // epilogue: bias + silu, direct stores
    int g = lane >> 2, tig = lane & 3;
    #pragma unroll
    for (int mt = 0; mt < 4; mt++) {
        int rg = row0 + warp_m * 64 + mt * 16 + g;
        #pragma unroll
        for (int nt = 0; nt < 4; nt++) {
            int cl = warp_n * 32 + nt * 8 + 2 * tig;
            float b0 = bias_s[cl], b1 = bias_s[cl + 1];
            float y0 = acc[mt][nt][0] + b0;
            float y1 = acc[mt][nt][1] + b1;
            float y2 = acc[mt][nt][2] + b0;
            float y3 = acc[mt][nt][3] + b1;
            float2 lo = make_float2(y0 * (1.f / (1.f + __expf(-y0))),
                                    y1 * (1.f / (1.f + __expf(-y1))));
            float2 hi = make_float2(y2 * (1.f / (1.f + __expf(-y2))),
                                    y3 * (1.f / (1.f + __expf(-y3))));
            *(float2*)(out + (size_t)rg * O_DIM + col0 + cl) = lo;
            *(float2*)(out + (size_t)(rg + 8) * O_DIM + col0 + cl) = hi;
        }
    }
}

// ================= launch =================
extern "C" void kernel_launch(void* const* d_in, const int* in_sizes, int n_in,
                              void* d_out, int out_size) {
    const float* x  = (const float*)d_in[0];   // [4096,1024]
    const float* C  = (const float*)d_in[1];   // [1024,1024,5]
    const float* w  = (const float*)d_in[2];   // [1024]
    const float* b  = (const float*)d_in[3];   // [1024]
    float* out = (float*)d_out;                // [4096,1024]

    cudaFuncSetAttribute(cheby_mma_gemm,
                         cudaFuncAttributeMaxDynamicSharedMemorySize, SMEM_TOTAL);

    ln_feat_kernel<<<B_DIM, 256>>>(x, w, b);
    prep_w_kernel<<<dim3(I_DIM / 32, O_DIM / 32), 256>>>(C);
    bias_kernel<<<O_DIM, 256>>>(C);
    cheby_mma_gemm<<<dim3(B_DIM / BM, O_DIM / BN), 256, SMEM_TOTAL>>>(out);
}

// round 8
// speedup vs baseline: 6.5585x; 1.0560x over previous
#include <cuda_runtime.h>
#include <cuda_fp16.h>
#include <math.h>
#include <stdint.h>

#define B_DIM 4096
#define I_DIM 1024
#define O_DIM 1024
#define KTOT  4096            // 4 degree planes * 1024

// ---- scratch (static device globals: no allocation anywhere) ----
__device__ __half g_A[(size_t)B_DIM * KTOT];   // fp16 Chebyshev features [b][k']
__device__ __half g_W[(size_t)O_DIM * KTOT];   // fp16 coeffs transposed  [o][k']
__device__ float  g_bias_part[32][O_DIM];      // per-i-block partial sums of C[:,o,0]
__device__ float  g_bias[O_DIM];               // sum_i C[i,o,0]

// ================= helpers =================
__device__ __forceinline__ uint32_t smem_u32(const void* p) {
    uint32_t a;
    asm("{ .reg .u64 t; cvta.to.shared.u64 t, %1; cvt.u32.u64 %0, t; }"
        : "=r"(a) : "l"(p));
    return a;
}
__device__ __forceinline__ void ldsm4(uint32_t* r, uint32_t addr) {
    asm volatile("ldmatrix.sync.aligned.m8n8.x4.shared.b16 {%0,%1,%2,%3}, [%4];"
                 : "=r"(r[0]), "=r"(r[1]), "=r"(r[2]), "=r"(r[3]) : "r"(addr));
}
__device__ __forceinline__ void mma16816(float* c, const uint32_t* a,
                                         uint32_t b0, uint32_t b1) {
    asm volatile(
        "mma.sync.aligned.m16n8k16.row.col.f32.f16.f16.f32 "
        "{%0,%1,%2,%3}, {%4,%5,%6,%7}, {%8,%9}, {%0,%1,%2,%3};"
        : "+f"(c[0]), "+f"(c[1]), "+f"(c[2]), "+f"(c[3])
        : "r"(a[0]), "r"(a[1]), "r"(a[2]), "r"(a[3]), "r"(b0), "r"(b1));
}
__device__ __forceinline__ void cpasync16(uint32_t dst, const void* src) {
    asm volatile("cp.async.cg.shared.global [%0], [%1], 16;" :: "r"(dst), "l"(src));
}

// ================= kernel 1: LN + tanh + Chebyshev features (fp16) =========
__global__ void ln_feat_kernel(const float* __restrict__ x,
                               const float* __restrict__ w,
                               const float* __restrict__ b) {
    int row = blockIdx.x;
    int tid = threadIdx.x;                 // 256 threads, 4 elements each
    float4 v = ((const float4*)(x + (size_t)row * I_DIM))[tid];
    float s  = v.x + v.y + v.z + v.w;
    float ss = v.x * v.x + v.y * v.y + v.z * v.z + v.w * v.w;
    #pragma unroll
    for (int o = 16; o > 0; o >>= 1) {
        s  += __shfl_down_sync(0xffffffffu, s, o);
        ss += __shfl_down_sync(0xffffffffu, ss, o);
    }
    __shared__ float rs[8], rss[8];
    __shared__ float s_mu, s_rstd;
    int wid = tid >> 5, lid = tid & 31;
    if (lid == 0) { rs[wid] = s; rss[wid] = ss; }
    __syncthreads();
    if (tid == 0) {
        float ts = 0.f, tss = 0.f;
        #pragma unroll
        for (int i = 0; i < 8; i++) { ts += rs[i]; tss += rss[i]; }
        float mu  = ts * (1.0f / I_DIM);
        float var = tss * (1.0f / I_DIM) - mu * mu;
        s_mu = mu; s_rstd = rsqrtf(var + 1e-5f);
    }
    __syncthreads();
    float mu = s_mu, rstd = s_rstd;
    float4 wv = ((const float4*)w)[tid];
    float4 bv = ((const float4*)b)[tid];
    float h[4];
    h[0] = tanhf((v.x - mu) * rstd * wv.x + bv.x);
    h[1] = tanhf((v.y - mu) * rstd * wv.y + bv.y);
    h[2] = tanhf((v.z - mu) * rstd * wv.z + bv.z);
    h[3] = tanhf((v.w - mu) * rstd * wv.w + bv.w);

    float t[4][4];                         // [degree-1][element]
    #pragma unroll
    for (int j = 0; j < 4; j++) {
        float h2 = h[j] + h[j];
        t[0][j] = h[j];
        t[1][j] = h2 * h[j] - 1.f;
        t[2][j] = h2 * t[1][j] - h[j];
        t[3][j] = h2 * t[2][j] - t[1][j];
    }
    int i0 = tid * 4;
    #pragma unroll
    for (int d = 0; d < 4; d++) {
        __half2 p0 = __floats2half2_rn(t[d][0], t[d][1]);
        __half2 p1 = __floats2half2_rn(t[d][2], t[d][3]);
        size_t off = (size_t)row * KTOT + d * I_DIM + i0;
        uint2 pk;
        pk.x = *(uint32_t*)&p0;
        pk.y = *(uint32_t*)&p1;
        *(uint2*)&g_A[off] = pk;
    }
}

// ============ kernel 2: coeff transpose to fp16 + d0 partial sums ==========
// C[i,o,d] -> g_W[o][d*1024+i]; also g_bias_part[i0/32][o] = sum_{r} C[i0+r,o,0]
__global__ void prep_w_kernel(const float* __restrict__ C) {
    __shared__ __align__(16) __half sh[4][32][36];
    __shared__ float sb[32][33];           // [c=o local][r=i local]
    int i0 = blockIdx.x * 32, o0 = blockIdx.y * 32;
    int tid = threadIdx.x;
    #pragma unroll
    for (int j = 0; j < 4; j++) {
        int p = tid + 256 * j;
        int r = p >> 5, c = p & 31;        // r = local i, c = local o
        const float* base = C + ((size_t)(i0 + r) * O_DIM + (o0 + c)) * 5;
        sb[c][r] = base[0];
        #pragma unroll
        for (int d = 0; d < 4; d++)
            sh[d][c][r] = __float2half_rn(base[d + 1]);
    }
    __syncthreads();
    int oc = tid >> 3, icb = (tid & 7) * 4;
    #pragma unroll
    for (int d = 0; d < 4; d++) {
        uint2 vh = *(const uint2*)&sh[d][oc][icb];
        size_t off = (size_t)(o0 + oc) * KTOT + d * I_DIM + i0 + icb;
        *(uint2*)&g_W[off] = vh;
    }
    if (tid < 32) {
        float s = 0.f;
        #pragma unroll
        for (int r = 0; r < 32; r++) s += sb[tid][r];
        g_bias_part[blockIdx.x][o0 + tid] = s;
    }
}

// ================= kernel 3: reduce bias partials (deterministic) ==========
__global__ void bias_reduce_kernel() {
    int o = blockIdx.x * 256 + threadIdx.x;
    float s = 0.f;
    #pragma unroll
    for (int k = 0; k < 32; k++) s += g_bias_part[k][o];
    g_bias[o] = s;
}

// ================= kernel 4: HMMA GEMM + bias + silu =================
// Block 128x128, 8 warps 2(m) x 4(n), warp tile 64x32; k-chunk 64,
// 3-stage cp.async pipeline, ONE __syncthreads per k-iter.
#define BM 128
#define BN 128
#define BKC 64
#define NT (KTOT / BKC)         // 64
#define TILE_BYTES (128 * 128)  // one operand tile: 128 rows * 128B
#define STAGE_BYTES (2 * TILE_BYTES)
#define SMEM_TOTAL (1024 + 3 * STAGE_BYTES)   // 99328 B; 2 CTAs/SM = 194KB

__global__ __launch_bounds__(256, 2) void cheby_mma_gemm(float* __restrict__ out) {
    extern __shared__ char smem[];
    float* bias_s = (float*)smem;
    char* tiles = smem + 1024;             // stage s: A at s*STAGE, B at +TILE

    int tid = threadIdx.x, lane = tid & 31, wid = tid >> 5;
    int warp_m = wid >> 2, warp_n = wid & 3;
    int row0 = blockIdx.x * BM, col0 = blockIdx.y * BN;
    if (tid < 128) bias_s[tid] = g_bias[col0 + tid];

    const __half* Ag = g_A + (size_t)row0 * KTOT;
    const __half* Wg = g_W + (size_t)col0 * KTOT;

    float acc[4][4][4];
    #pragma unroll
    for (int mt = 0; mt < 4; mt++)
        #pragma unroll
        for (int nt = 0; nt < 4; nt++)
            #pragma unroll
            for (int q2 = 0; q2 < 4; q2++) acc[mt][nt][q2] = 0.f;

    // per-thread load slots: 4 x 16B per operand tile
    int ldr[4], ldc[4], ldo[4];
    #pragma unroll
    for (int j = 0; j < 4; j++) {
        int ch = tid + 256 * j;            // 1024 chunks of 16B
        ldr[j] = ch >> 3;
        ldc[j] = ch & 7;
        ldo[j] = ldr[j] * 128 + ((ldc[j] ^ (ldr[j] & 7)) << 4);
    }

    // preload stages 0 and 1
    #pragma unroll
    for (int pre = 0; pre < 2; pre++) {
        uint32_t ad = smem_u32(tiles + pre * STAGE_BYTES);
        uint32_t bd = ad + TILE_BYTES;
        int kb = pre * BKC;
        #pragma unroll
        for (int j = 0; j < 4; j++) {
            cpasync16(ad + ldo[j], Ag + (size_t)ldr[j] * KTOT + kb + ldc[j] * 8);
            cpasync16(bd + ldo[j], Wg + (size_t)ldr[j] * KTOT + kb + ldc[j] * 8);
        }
        asm volatile("cp.async.commit_group;");
    }

    int q = lane >> 3, lr = lane & 7;
    int stage = 0;

    for (int t = 0; t < NT; t++) {
        if (t < NT - 1) asm volatile("cp.async.wait_group 1;");
        else            asm volatile("cp.async.wait_group 0;");
        __syncthreads();

        uint32_t abase = smem_u32(tiles + stage * STAGE_BYTES);
        uint32_t bbase = abase + TILE_BYTES;

        #pragma unroll
        for (int s = 0; s < 4; s++) {
            uint32_t a[4][4];
            #pragma unroll
            for (int mt = 0; mt < 4; mt++) {
                int r = warp_m * 64 + mt * 16 + lr + (q & 1) * 8;
                int c16 = 2 * s + (q >> 1);
                ldsm4(a[mt], abase + r * 128 + ((c16 ^ (r & 7)) << 4));
            }
            uint32_t bfr[2][4];
            #pragma unroll
            for (int p = 0; p < 2; p++) {
                int r = warp_n * 32 + p * 16 + lr + (q >> 1) * 8;
                int c16 = 2 * s + (q & 1);
                ldsm4(bfr[p], bbase + r * 128 + ((c16 ^ (r & 7)) << 4));
            }
            #pragma unroll
            for (int mt = 0; mt < 4; mt++) {
                #pragma unroll
                for (int nt = 0; nt < 4; nt++) {
                    int p = nt >> 1, e = (nt & 1) * 2;
                    mma16816(acc[mt][nt], a[mt], bfr[p][e], bfr[p][e + 1]);
                }
            }
        }

        // issue loads for stage t+2 (lands during the next full iteration)
        if (t + 2 < NT) {
            int wstage = (stage + 2 == 3) ? 2 : (stage + 2) % 3;
            uint32_t ad = smem_u32(tiles + ((stage + 2) % 3) * STAGE_BYTES);
            uint32_t bd = ad + TILE_BYTES;
            int kb = (t + 2) * BKC;
            (void)wstage;
            #pragma unroll
            for (int j = 0; j < 4; j++) {
                cpasync16(ad + ldo[j], Ag + (size_t)ldr[j] * KTOT + kb + ldc[j] * 8);
                cpasync16(bd + ldo[j], Wg + (size_t)ldr[j] * KTOT + kb + ldc[j] * 8);
            }
            asm volatile("cp.async.commit_group;");
        } else {
            // keep group accounting consistent for the wait at loop top
            asm volatile("cp.async.commit_group;");
        }
        stage = (stage + 1) % 3;
    }

    // epilogue: bias + silu, direct stores
    int g = lane >> 2, tig = lane & 3;
    #pragma unroll
    for (int mt = 0; mt < 4; mt++) {
        int rg = row0 + warp_m * 64 + mt * 16 + g;
        #pragma unroll
        for (int nt = 0; nt < 4; nt++) {
            int cl = warp_n * 32 + nt * 8 + 2 * tig;
            float b0 = bias_s[cl], b1 = bias_s[cl + 1];
            float y0 = acc[mt][nt][0] + b0;
            float y1 = acc[mt][nt][1] + b1;
            float y2 = acc[mt][nt][2] + b0;
            float y3 = acc[mt][nt][3] + b1;
            float2 lo = make_float2(y0 * (1.f / (1.f + __expf(-y0))),
                                    y1 * (1.f / (1.f + __expf(-y1))));
            float2 hi = make_float2(y2 * (1.f / (1.f + __expf(-y2))),
                                    y3 * (1.f / (1.f + __expf(-y3))));
            *(float2*)(out + (size_t)rg * O_DIM + col0 + cl) = lo;
            *(float2*)(out + (size_t)(rg + 8) * O_DIM + col0 + cl) = hi;
        }
    }
}

// ================= launch =================
extern "C" void kernel_launch(void* const* d_in, const int* in_sizes, int n_in,
                              void* d_out, int out_size) {
    const float* x  = (const float*)d_in[0];   // [4096,1024]
    const float* C  = (const float*)d_in[1];   // [1024,1024,5]
    const float* w  = (const float*)d_in[2];   // [1024]
    const float* b  = (const float*)d_in[3];   // [1024]
    float* out = (float*)d_out;                // [4096,1024]

    cudaFuncSetAttribute(cheby_mma_gemm,
                         cudaFuncAttributeMaxDynamicSharedMemorySize, SMEM_TOTAL);

    ln_feat_kernel<<<B_DIM, 256>>>(x, w, b);
    prep_w_kernel<<<dim3(I_DIM / 32, O_DIM / 32), 256>>>(C);
    bias_reduce_kernel<<<O_DIM / 256, 256>>>();
    cheby_mma_gemm<<<dim3(B_DIM / BM, O_DIM / BN), 256, SMEM_TOTAL>>>(out);
}